// round 1
// baseline (speedup 1.0000x reference)
#include <cuda_runtime.h>
#include <stdint.h>

// StridedSlice: out[n,c,h,w] = x[n,c,2h,2w]
//   in : (8,128,512,512) f32  -> per (n,c,h) input row = 512 floats = 128 float4
//   out: (8,128,256,256) f32  -> per (n,c,h) output row = 256 floats = 64 float4
//
// Each thread produces 2 consecutive float4 outputs (8 out floats) from
// 4 consecutive float4 loads (16 in floats = 64 contiguous bytes).
// Everything is power-of-two -> shifts/masks for indexing.

__global__ __launch_bounds__(256) void strided_slice_kernel(
    const float4* __restrict__ in, float4* __restrict__ out)
{
    // pair index: each pair = 2 float4 outputs.
    // total out float4 = 8*128*256*256/4 = 16,777,216 -> 8,388,608 pairs
    unsigned p = blockIdx.x * 256u + threadIdx.x;

    unsigned w8  = p & 31u;        // 32 pairs per output row (64 float4 / 2)
    unsigned row = p >> 5;         // combined (n*c, h) row index, 262144 rows
    unsigned h   = row & 255u;
    unsigned nc  = row >> 8;

    // input offsets in float4 units:
    //   plane (per nc) = 512*512/4 = 65536 float4
    //   row stride     = 512/4     = 128 float4
    //   w8 pair start  = 4 float4 in (covers 16 input floats)
    const float4* src = in + ((size_t)nc << 16) + ((size_t)(h << 1) << 7) + (w8 << 2);

    float4 a = src[0];
    float4 b = src[1];
    float4 c = src[2];
    float4 d = src[3];

    float4* dst = out + ((size_t)p << 1);
    dst[0] = make_float4(a.x, a.z, b.x, b.z);
    dst[1] = make_float4(c.x, c.z, d.x, d.z);
}

extern "C" void kernel_launch(void* const* d_in, const int* in_sizes, int n_in,
                              void* d_out, int out_size)
{
    (void)in_sizes; (void)n_in; (void)out_size;
    const float4* in  = (const float4*)d_in[0];
    float4*       out = (float4*)d_out;

    // 8,388,608 pairs / 256 threads = 32768 blocks
    strided_slice_kernel<<<32768, 256>>>(in, out);
}

// round 2
// speedup vs baseline: 1.1369x; 1.1369x over previous
#include <cuda_runtime.h>
#include <stdint.h>

// StridedSlice: out[n,c,h,w] = x[n,c,2h,2w]
//   in : (8,128,512,512) f32   in row = 512 f32 = 128 float4, plane = 65536 float4
//   out: (8,128,256,256) f32   out row = 256 f32 = 64 float4
//
// One warp produces 2 consecutive output rows (128 float4 = 2 KB) from
// 2 input rows (2h, 2h+2 -> 4 KB). Thread t writes out float4 {t,32+t,64+t,96+t}
// (fully coalesced STG.128). Each output float4 consumes one aligned 32B input
// sector, loaded as two LDG.128 at lane-stride 32B (50% wavefront efficiency,
// 100% sector efficiency, lines fully consumed across the instruction pair).

__global__ __launch_bounds__(256) void strided_slice_kernel(
    const float4* __restrict__ in, float4* __restrict__ out)
{
    unsigned wg = (blockIdx.x * 256u + threadIdx.x) >> 5;  // global warp id
    unsigned t  = threadIdx.x & 31u;

    unsigned r0 = wg << 1;          // first output row handled by this warp
    unsigned h  = r0 & 255u;        // even; r0+1 stays in the same plane
    unsigned nc = r0 >> 8;

    // input base for output row r0: plane nc, input row 2h  -> (2h)*128 = h<<8
    const float4* __restrict__ ib = in + ((size_t)nc << 16) + ((size_t)h << 8);
    float4* __restrict__ ob = out + ((size_t)r0 << 6);      // r0 * 64

    unsigned t2 = t << 1;

    // output row r0  (input row 2h): 8 front-batched LDG.128
    float4 a0 = __ldg(ib + t2);            // sector pair (cols 0..63 of out row)
    float4 a1 = __ldg(ib + t2 + 1);
    float4 a2 = __ldg(ib + t2 + 64);       // cols 32..63
    float4 a3 = __ldg(ib + t2 + 65);
    // output row r0+1 (input row 2h+2 -> +256 float4)
    float4 b0 = __ldg(ib + t2 + 256);
    float4 b1 = __ldg(ib + t2 + 257);
    float4 b2 = __ldg(ib + t2 + 320);
    float4 b3 = __ldg(ib + t2 + 321);

    ob[t]      = make_float4(a0.x, a0.z, a1.x, a1.z);
    ob[32 + t] = make_float4(a2.x, a2.z, a3.x, a3.z);
    ob[64 + t] = make_float4(b0.x, b0.z, b1.x, b1.z);
    ob[96 + t] = make_float4(b2.x, b2.z, b3.x, b3.z);
}

extern "C" void kernel_launch(void* const* d_in, const int* in_sizes, int n_in,
                              void* d_out, int out_size)
{
    (void)in_sizes; (void)n_in; (void)out_size;
    const float4* in  = (const float4*)d_in[0];
    float4*       out = (float4*)d_out;

    // 262144 output rows / 2 rows per warp = 131072 warps
    // = 4,194,304 threads = 16384 blocks of 256
    strided_slice_kernel<<<16384, 256>>>(in, out);
}

// round 3
// speedup vs baseline: 1.1376x; 1.0005x over previous
#include <cuda_runtime.h>
#include <stdint.h>

// StridedSlice: out[n,c,h,w] = x[n,c,2h,2w]
//   in : (8,128,512,512) f32   in row = 128 float4, plane = 65536 float4
//   out: (8,128,256,256) f32   out row = 64 float4, 262144 rows total
//
// One warp produces 4 consecutive output rows (256 float4 = 4 KB) from
// 4 even input rows (8 KB). Thread t writes out float4 {32j+t} per row
// (fully coalesced STG.128). Each output float4 consumes one aligned 32B
// input sector via two LDG.128 at lane-stride 32B. 16 loads front-batched
// (MLP_p1=16). Streaming hints: zero reuse -> evict-first in L1/L2.

__global__ __launch_bounds__(256) void strided_slice_kernel(
    const float4* __restrict__ in, float4* __restrict__ out)
{
    unsigned wg = (blockIdx.x * 256u + threadIdx.x) >> 5;  // global warp id
    unsigned t  = threadIdx.x & 31u;

    unsigned r0 = wg << 2;          // first of 4 output rows for this warp
    unsigned h  = r0 & 255u;        // multiple of 4; rows stay in one plane
    unsigned nc = r0 >> 8;

    const float4* __restrict__ ib = in + ((size_t)nc << 16) + ((size_t)h << 8);
    float4* __restrict__ ob = out + ((size_t)r0 << 6);

    unsigned t2 = t << 1;

    // 16 front-batched streaming loads (4 rows x 4 float4)
    float4 a0 = __ldcs(ib + t2);
    float4 a1 = __ldcs(ib + t2 + 1);
    float4 a2 = __ldcs(ib + t2 + 64);
    float4 a3 = __ldcs(ib + t2 + 65);
    float4 b0 = __ldcs(ib + t2 + 256);
    float4 b1 = __ldcs(ib + t2 + 257);
    float4 b2 = __ldcs(ib + t2 + 320);
    float4 b3 = __ldcs(ib + t2 + 321);
    float4 c0 = __ldcs(ib + t2 + 512);
    float4 c1 = __ldcs(ib + t2 + 513);
    float4 c2 = __ldcs(ib + t2 + 576);
    float4 c3 = __ldcs(ib + t2 + 577);
    float4 d0 = __ldcs(ib + t2 + 768);
    float4 d1 = __ldcs(ib + t2 + 769);
    float4 d2 = __ldcs(ib + t2 + 832);
    float4 d3 = __ldcs(ib + t2 + 833);

    __stcs(ob + t,        make_float4(a0.x, a0.z, a1.x, a1.z));
    __stcs(ob + 32 + t,   make_float4(a2.x, a2.z, a3.x, a3.z));
    __stcs(ob + 64 + t,   make_float4(b0.x, b0.z, b1.x, b1.z));
    __stcs(ob + 96 + t,   make_float4(b2.x, b2.z, b3.x, b3.z));
    __stcs(ob + 128 + t,  make_float4(c0.x, c0.z, c1.x, c1.z));
    __stcs(ob + 160 + t,  make_float4(c2.x, c2.z, c3.x, c3.z));
    __stcs(ob + 192 + t,  make_float4(d0.x, d0.z, d1.x, d1.z));
    __stcs(ob + 224 + t,  make_float4(d2.x, d2.z, d3.x, d3.z));
}

extern "C" void kernel_launch(void* const* d_in, const int* in_sizes, int n_in,
                              void* d_out, int out_size)
{
    (void)in_sizes; (void)n_in; (void)out_size;
    const float4* in  = (const float4*)d_in[0];
    float4*       out = (float4*)d_out;

    // 262144 output rows / 4 rows per warp = 65536 warps = 8192 blocks of 256
    strided_slice_kernel<<<8192, 256>>>(in, out);
}